// round 14
// baseline (speedup 1.0000x reference)
#include <cuda_runtime.h>
#include <math.h>

// ---------------------------------------------------------------------------
// Problem constants
// ---------------------------------------------------------------------------
#define DW 128
#define DH 128
#define DD 128
#define NV (DW*DH*DD)          // 2097152 voxels
#define NS 16
#define HSL 128
#define WSL 128
#define PIX (HSL*WSL)
#define RES 1.5f
#define N_ITER 10

// ---------------------------------------------------------------------------
// Persistent state (device globals -> no allocations anywhere)
// ---------------------------------------------------------------------------
__device__ float g_b[NV];
__device__ float g_x[NV];
__device__ float g_r[NV];
__device__ float g_p[NV];
__device__ float g_Ap[NV];
// per-iteration CG scalars (double accumulators)
__device__ double g_pAp[16];
__device__ double g_rr[16];
// grid-barrier state for k_upAP (reset each replay by k_zero)
__device__ unsigned g_arr;
__device__ unsigned g_rel;

// ---------------------------------------------------------------------------
// Block reduction -> atomicAdd(double)
// ---------------------------------------------------------------------------
__device__ __forceinline__ void reduce_add(double val, double* target)
{
    #pragma unroll
    for (int o = 16; o > 0; o >>= 1)
        val += __shfl_down_sync(0xffffffffu, val, o);
    __shared__ double sm[32];
    int lane = threadIdx.x & 31, wid = threadIdx.x >> 5;
    if (lane == 0) sm[wid] = val;
    __syncthreads();
    if (wid == 0) {
        val = (lane < (int)(blockDim.x >> 5)) ? sm[lane] : 0.0;
        #pragma unroll
        for (int o = 16; o > 0; o >>= 1)
            val += __shfl_down_sync(0xffffffffu, val, o);
        if (lane == 0) atomicAdd(target, val);
    }
}

// ---------------------------------------------------------------------------
// Forward gather of one PSF tap (OOB corners contribute 0, as in reference).
// ---------------------------------------------------------------------------
__device__ __forceinline__ float gather_tap(const float* __restrict__ v,
                                            float px, float py, float pz)
{
    if (px <= -1.f || px >= 128.f || py <= -1.f || py >= 128.f ||
        pz <= -1.f || pz >= 128.f)
        return 0.f;

    float xf = floorf(px), yf = floorf(py), zf = floorf(pz);
    int ix = (int)xf, iy = (int)yf, iz = (int)zf;
    float fx = px - xf, fy = py - yf, fz = pz - zf;
    float gx = 1.f - fx, gy = 1.f - fy, gz = 1.f - fz;

    if (ix >= 0 && ix < DW-1 && iy >= 0 && iy < DH-1 && iz >= 0 && iz < DD-1) {
        const float* b0 = v + ((iz*DH + iy)*DW + ix);
        const float* b1 = b0 + DH*DW;
        float v000 = __ldg(b0),      v100 = __ldg(b0+1);
        float v010 = __ldg(b0+DW),   v110 = __ldg(b0+DW+1);
        float v001 = __ldg(b1),      v101 = __ldg(b1+1);
        float v011 = __ldg(b1+DW),   v111 = __ldg(b1+DW+1);
        return gz*(gy*(gx*v000 + fx*v100) + fy*(gx*v010 + fx*v110))
             + fz*(gy*(gx*v001 + fx*v101) + fy*(gx*v011 + fx*v111));
    }

    float acc = 0.f;
    #pragma unroll
    for (int dz = 0; dz < 2; dz++)
    #pragma unroll
    for (int dy = 0; dy < 2; dy++)
    #pragma unroll
    for (int dx = 0; dx < 2; dx++) {
        int X = ix + dx, Y = iy + dy, Z = iz + dz;
        if (X >= 0 && X < DW && Y >= 0 && Y < DH && Z >= 0 && Z < DD) {
            float w = (dx ? fx : gx) * (dy ? fy : gy) * (dz ? fz : gz);
            acc += w * __ldg(v + ((Z*DH + Y)*DW + X));
        }
    }
    return acc;
}

// ---------------------------------------------------------------------------
// Scatter-add of one PSF tap (exact adjoint; uniform scalar REDs).
// ---------------------------------------------------------------------------
__device__ __forceinline__ void scatter_tap(float* __restrict__ v,
                                            float px, float py, float pz, float c)
{
    if (px <= -1.f || px >= 128.f || py <= -1.f || py >= 128.f ||
        pz <= -1.f || pz >= 128.f)
        return;

    float xf = floorf(px), yf = floorf(py), zf = floorf(pz);
    int ix = (int)xf, iy = (int)yf, iz = (int)zf;
    float fx = px - xf, fy = py - yf, fz = pz - zf;
    float gx = 1.f - fx, gy = 1.f - fy, gz = 1.f - fz;

    if (ix >= 0 && ix < DW-1 && iy >= 0 && iy < DH-1 && iz >= 0 && iz < DD-1) {
        float* b0 = v + ((iz*DH + iy)*DW + ix);
        float* b1 = b0 + DH*DW;
        float w00 = c*gz*gy, w01 = c*gz*fy, w10 = c*fz*gy, w11 = c*fz*fy;
        atomicAdd(b0,       w00*gx);
        atomicAdd(b0+1,     w00*fx);
        atomicAdd(b0+DW,    w01*gx);
        atomicAdd(b0+DW+1,  w01*fx);
        atomicAdd(b1,       w10*gx);
        atomicAdd(b1+1,     w10*fx);
        atomicAdd(b1+DW,    w11*gx);
        atomicAdd(b1+DW+1,  w11*fx);
        return;
    }

    #pragma unroll
    for (int dz = 0; dz < 2; dz++)
    #pragma unroll
    for (int dy = 0; dy < 2; dy++)
    #pragma unroll
    for (int dx = 0; dx < 2; dx++) {
        int X = ix + dx, Y = iy + dy, Z = iz + dz;
        if (X >= 0 && X < DW && Y >= 0 && Y < DH && Z >= 0 && Z < DD) {
            float w = (dx ? fx : gx) * (dy ? fy : gy) * (dz ? fz : gz);
            atomicAdd(v + ((Z*DH + Y)*DW + X), c*w);
        }
    }
}

// ---------------------------------------------------------------------------
// Per-slice PSF tap constants into shared memory.
// ---------------------------------------------------------------------------
__device__ __forceinline__ void load_slice_consts(const float* __restrict__ theta,
                                                  const float* __restrict__ psf,
                                                  int n, float sR[9],
                                                  float sC[27][3], float sPsf[27])
{
    int t = threadIdx.x;
    if (t < 9) sR[t] = theta[n*12 + (t/3)*4 + (t%3)];
    __syncthreads();
    if (t < 27) {
        float ox = (float)(t % 3)       - 1.f;
        float oy = (float)((t / 3) % 3) - 1.f;
        float oz = (float)(t / 9)       - 1.f;
        float tx = theta[n*12 + 3],  ty = theta[n*12 + 7],  tz = theta[n*12 + 11];
        sC[t][0] = sR[0]*ox + sR[1]*oy + sR[2]*oz + tx + 63.5f;
        sC[t][1] = sR[3]*ox + sR[4]*oy + sR[5]*oz + ty + 63.5f;
        sC[t][2] = sR[6]*ox + sR[7]*oy + sR[8]*oz + tz + 63.5f;
        sPsf[t]  = psf[t];
    }
    __syncthreads();
}

// ---------------------------------------------------------------------------
// Fused AtA (R8 form — at the REDG floor, do not touch):
// sval = (A v)_pix; pAp[slot] += sval^2 (== p.AtAp); scatter into g_Ap.
// grid = (64, 1, 16), block = 256.  ALL threads reach the reduction.
// ---------------------------------------------------------------------------
__global__ void __launch_bounds__(256)
k_AtA(const float* __restrict__ theta, const float* __restrict__ psf,
      const float* __restrict__ v, int pAp_slot)
{
    __shared__ float sR[9];
    __shared__ float sC[27][3];
    __shared__ float sPsf[27];
    int n = blockIdx.z;
    load_slice_consts(theta, psf, n, sR, sC, sPsf);

    int pix = blockIdx.x * blockDim.x + threadIdx.x;
    int w = pix & (WSL-1);
    int h = pix >> 7;
    float u  = ((float)w - 63.5f) * RES;
    float vv = ((float)h - 63.5f) * RES;
    float bx = sR[0]*u + sR[1]*vv;
    float by = sR[3]*u + sR[4]*vv;
    float bz = sR[6]*u + sR[7]*vv;

    float sval = 0.f;
    // conservative whole-pixel reject: center tap (k=13) within margin 3
    float cx = bx + sC[13][0], cy = by + sC[13][1], cz = bz + sC[13][2];
    if (cx > -3.f && cx < 130.f && cy > -3.f && cy < 130.f &&
        cz > -3.f && cz < 130.f) {
        for (int k = 0; k < 27; k++)
            sval += sPsf[k] * gather_tap(v, bx + sC[k][0], by + sC[k][1],
                                            bz + sC[k][2]);
    }
    reduce_add((double)sval * (double)sval, &g_pAp[pAp_slot]);
    if (sval != 0.f) {
        for (int k = 0; k < 27; k++)
            scatter_tap(g_Ap, bx + sC[k][0], by + sC[k][1], bz + sC[k][2],
                        sval * sPsf[k]);
    }
}

// ---------------------------------------------------------------------------
// b = At(slices): scatter raw slice values into g_b (pre-zeroed).
// ---------------------------------------------------------------------------
__global__ void __launch_bounds__(256)
k_At_b(const float* __restrict__ theta, const float* __restrict__ psf,
       const float* __restrict__ slices)
{
    __shared__ float sR[9];
    __shared__ float sC[27][3];
    __shared__ float sPsf[27];
    int n = blockIdx.z;
    load_slice_consts(theta, psf, n, sR, sC, sPsf);

    int pix = blockIdx.x * blockDim.x + threadIdx.x;
    int w = pix & (WSL-1);
    int h = pix >> 7;
    float u  = ((float)w - 63.5f) * RES;
    float vv = ((float)h - 63.5f) * RES;
    float bx = sR[0]*u + sR[1]*vv;
    float by = sR[3]*u + sR[4]*vv;
    float bz = sR[6]*u + sR[7]*vv;

    float cx = bx + sC[13][0], cy = by + sC[13][1], cz = bz + sC[13][2];
    if (cx < -3.f || cx > 130.f || cy < -3.f || cy > 130.f ||
        cz < -3.f || cz > 130.f)
        return;

    float sval = slices[n * PIX + pix];
    for (int k = 0; k < 27; k++)
        scatter_tap(g_b, bx + sC[k][0], by + sC[k][1], bz + sC[k][2],
                    sval * sPsf[k]);
}

// ---------------------------------------------------------------------------
// Elementwise kernels.
// ---------------------------------------------------------------------------
#define F4(ptr) (reinterpret_cast<float4*>(ptr))
#define CF4(ptr) (reinterpret_cast<const float4*>(ptr))
#define HALF4 (NV/8)     // 262144 float4 per half  (1024-block kernels)
#define QUART4 (NV/16)   // 131072 float4 per quarter (512-block k_upAP)

// zero b, Ap, scalars, barrier counters (1024 blocks, 2x float4/thread)
__global__ void __launch_bounds__(256)
k_zero()
{
    int i = blockIdx.x * blockDim.x + threadIdx.x;
    float4 z = make_float4(0.f, 0.f, 0.f, 0.f);
    F4(g_b)[i]          = z;
    F4(g_b)[i + HALF4]  = z;
    F4(g_Ap)[i]         = z;
    F4(g_Ap)[i + HALF4] = z;
    if (blockIdx.x == 0 && threadIdx.x == 0) { g_arr = 0u; g_rel = 0u; }
    if (blockIdx.x == 0 && threadIdx.x < 16) {
        g_pAp[threadIdx.x] = 0.0;
        g_rr[threadIdx.x]  = 0.0;
    }
}

__global__ void __launch_bounds__(256)
k_copy_x(const float* __restrict__ volume)
{
    int i = blockIdx.x * blockDim.x + threadIdx.x;
    F4(g_x)[i]         = CF4(volume)[i];
    F4(g_x)[i + HALF4] = CF4(volume)[i + HALF4];
}

// r = b - Ap ; p = r ; rr[0] += r.r ; Ap = 0   (1024 blocks)
__global__ void __launch_bounds__(256)
k_init_rp()
{
    int i0 = blockIdx.x * blockDim.x + threadIdx.x;
    double acc = 0.0;
    float4 z = make_float4(0.f, 0.f, 0.f, 0.f);
    #pragma unroll
    for (int half = 0; half < 2; half++) {
        int i = i0 + half * HALF4;
        float4 b4 = F4(g_b)[i];
        float4 a4 = F4(g_Ap)[i];
        float4 r4 = make_float4(b4.x - a4.x, b4.y - a4.y, b4.z - a4.z, b4.w - a4.w);
        F4(g_r)[i] = r4;
        F4(g_p)[i] = r4;
        F4(g_Ap)[i] = z;
        acc += (double)r4.x*r4.x + (double)r4.y*r4.y
             + (double)r4.z*r4.z + (double)r4.w*r4.w;
    }
    reduce_add(acc, &g_rr[0]);
}

// ---------------------------------------------------------------------------
// Fused CG update (upA + upP in one launch via in-kernel grid barrier).
// grid = 512 blocks x 256 thr, 4 float4s (16 elems) per thread.
// Deadlock-safety: __launch_bounds__(256,4) guarantees occupancy >= 4
// blocks/SM (1024 thr/SM = 50% of ceiling, regs <= 64).  Capacity
// 4*148 = 592 > 512 -> all blocks are wave-1 co-resident, with margin.
//  phase1: alpha = rr[it]/pAp[it]; x += alpha p; r -= alpha Ap; Ap = 0;
//          rr[it+1] += r.r
//  barrier
//  phase2 (skipped on last iter): beta = rr[it+1]/rr[it]; p = r + beta p
// ---------------------------------------------------------------------------
__global__ void __launch_bounds__(256, 4)
k_upAP(int it)
{
    float alpha = (float)(g_rr[it] / g_pAp[it]);
    int i0 = blockIdx.x * blockDim.x + threadIdx.x;
    double acc = 0.0;
    float4 z = make_float4(0.f, 0.f, 0.f, 0.f);
    #pragma unroll
    for (int q = 0; q < 4; q++) {
        int i = i0 + q * QUART4;
        float4 p4 = F4(g_p)[i];
        float4 a4 = F4(g_Ap)[i];
        float4 x4 = F4(g_x)[i];
        float4 r4 = F4(g_r)[i];
        x4.x += alpha*p4.x; x4.y += alpha*p4.y;
        x4.z += alpha*p4.z; x4.w += alpha*p4.w;
        r4.x -= alpha*a4.x; r4.y -= alpha*a4.y;
        r4.z -= alpha*a4.z; r4.w -= alpha*a4.w;
        F4(g_x)[i] = x4;
        F4(g_r)[i] = r4;
        F4(g_Ap)[i] = z;
        acc += (double)r4.x*r4.x + (double)r4.y*r4.y
             + (double)r4.z*r4.z + (double)r4.w*r4.w;
    }
    reduce_add(acc, &g_rr[it + 1]);   // tid0 (warp0 lane0) issues block's atomic

    if (it == N_ITER - 1) return;     // p never used again; no barrier needed

    // ---- grid barrier (tid0 arrives+spins; block released via syncthreads)
    __shared__ float s_beta;
    if (threadIdx.x == 0) {
        __threadfence();                               // rr atomic before arrive
        unsigned a = atomicAdd(&g_arr, 1u) + 1u;
        unsigned arr_target = (unsigned)(it + 1) * gridDim.x;
        if (a == arr_target) atomicAdd(&g_rel, 1u);
        unsigned rel_target = (unsigned)(it + 1);
        while (atomicAdd(&g_rel, 0u) < rel_target) __nanosleep(64);
        // atomic read of rr[it+1]: its cache line may be L1-stale here
        double rr_new = atomicAdd(&g_rr[it + 1], 0.0);
        s_beta = (float)(rr_new / g_rr[it]);
    }
    __syncthreads();

    // ---- phase 2: p = r + beta p (owner re-reads own lines: L2 hits)
    float beta = s_beta;
    #pragma unroll
    for (int q = 0; q < 4; q++) {
        int i = i0 + q * QUART4;
        float4 r4 = F4(g_r)[i];
        float4 p4 = F4(g_p)[i];
        F4(g_p)[i] = make_float4(r4.x + beta*p4.x, r4.y + beta*p4.y,
                                 r4.z + beta*p4.z, r4.w + beta*p4.w);
    }
}

__global__ void __launch_bounds__(256)
k_relu_out(float* __restrict__ out)
{
    int i0 = blockIdx.x * blockDim.x + threadIdx.x;
    #pragma unroll
    for (int half = 0; half < 2; half++) {
        int i = i0 + half * HALF4;
        float4 x4 = F4(g_x)[i];
        F4(out)[i] = make_float4(fmaxf(x4.x, 0.f), fmaxf(x4.y, 0.f),
                                 fmaxf(x4.z, 0.f), fmaxf(x4.w, 0.f));
    }
}

// ---------------------------------------------------------------------------
// Host driver (graph-capturable: kernel launches only)
// ---------------------------------------------------------------------------
extern "C" void kernel_launch(void* const* d_in, const int* in_sizes, int n_in,
                              void* d_out, int out_size)
{
    const float *theta = nullptr, *slices = nullptr, *volume = nullptr, *psf = nullptr;
    for (int i = 0; i < n_in; i++) {
        switch (in_sizes[i]) {
            case NS*12:   theta  = (const float*)d_in[i]; break;
            case NS*PIX:  slices = (const float*)d_in[i]; break;
            case NV:      volume = (const float*)d_in[i]; break;
            case 27:      psf    = (const float*)d_in[i]; break;
            default: break;
        }
    }
    float* out = (float*)d_out;

    float *p;
    cudaGetSymbolAddress((void**)&p, g_p);

    const int V8B = NV / 8 / 256;                  // 1024
    const int UPB = 512;                           // k_upAP grid (co-resident)
    const dim3 gridS(PIX / 256, 1, NS);            // (64,1,16)

    // Launch #4 is what ncu captures -> keep it k_AtA.
    k_zero<<<V8B, 256>>>();                          // 1: zero b, Ap, scalars, barrier
    k_At_b<<<gridS, 256>>>(theta, psf, slices);      // 2: b = At(slices)
    k_copy_x<<<V8B, 256>>>(volume);                  // 3: x = x0
    k_AtA<<<gridS, 256>>>(theta, psf, volume, 15);   // 4: Ap = AtA(x0)  [profiled]
    k_init_rp<<<V8B, 256>>>();                       // 5: r = p = b-Ap; rr[0]; Ap=0

    for (int it = 0; it < N_ITER; it++) {
        k_AtA<<<gridS, 256>>>(theta, psf, p, it);    // Ap = AtA(p); pAp[it]
        k_upAP<<<UPB, 256>>>(it);                    // x,r,rr[it+1]; barrier; p
    }

    k_relu_out<<<V8B, 256>>>(out);
    (void)out_size;
}